// round 9
// baseline (speedup 1.0000x reference)
#include <cuda_runtime.h>
#include <cuda_bf16.h>
#include <stdint.h>

// ===========================================================================
// JAX threefry2x32 (exact), rotate via funnel shift
// ===========================================================================
__host__ __device__ __forceinline__ void threefry2x32_host(
    uint32_t k0, uint32_t k1, uint32_t x0, uint32_t x1,
    uint32_t& o0, uint32_t& o1)
{
    uint32_t ks2 = k0 ^ k1 ^ 0x1BD11BDAu;
    x0 += k0; x1 += k1;
#define TF_RNDH(R) { x0 += x1; x1 = (x1 << (R)) | (x1 >> (32 - (R))); x1 ^= x0; }
    TF_RNDH(13) TF_RNDH(15) TF_RNDH(26) TF_RNDH(6)   x0 += k1;  x1 += ks2 + 1u;
    TF_RNDH(17) TF_RNDH(29) TF_RNDH(16) TF_RNDH(24)  x0 += ks2; x1 += k0  + 2u;
    TF_RNDH(13) TF_RNDH(15) TF_RNDH(26) TF_RNDH(6)   x0 += k0;  x1 += k1  + 3u;
    TF_RNDH(17) TF_RNDH(29) TF_RNDH(16) TF_RNDH(24)  x0 += k1;  x1 += ks2 + 4u;
    TF_RNDH(13) TF_RNDH(15) TF_RNDH(26) TF_RNDH(6)   x0 += ks2; x1 += k0  + 5u;
#undef TF_RNDH
    o0 = x0; o1 = x1;
}

// keep-decision for flat element e: partitionable threefry counter (0, e),
// XOR-fold, then uniform<0.8f as an EXACT integer compare:
//   u = m*2^-23 (m = bits>>9), 0.8f = 6710886.5*2^-23
//   u < 0.8f  <=>  m <= 0x666666  <=>  bits < 0xCCCCCE00   (R8 bug: CC00)
__device__ __forceinline__ uint32_t tf_keep(uint32_t k0, uint32_t k1, uint32_t ks2,
                                            uint32_t e)
{
    uint32_t x0 = k0, x1 = e + k1;
#define TF_RND(R) { x0 += x1; x1 = __funnelshift_l(x1, x1, R); x1 ^= x0; }
    TF_RND(13) TF_RND(15) TF_RND(26) TF_RND(6)   x0 += k1;  x1 += ks2 + 1u;
    TF_RND(17) TF_RND(29) TF_RND(16) TF_RND(24)  x0 += ks2; x1 += k0  + 2u;
    TF_RND(13) TF_RND(15) TF_RND(26) TF_RND(6)   x0 += k0;  x1 += k1  + 3u;
    TF_RND(17) TF_RND(29) TF_RND(16) TF_RND(24)  x0 += k1;  x1 += ks2 + 4u;
    TF_RND(13) TF_RND(15) TF_RND(26) TF_RND(6)   x0 += ks2; x1 += k0  + 5u;
#undef TF_RND
    return ((x0 ^ x1) < 0xCCCCCE00u) ? 1u : 0u;
}

// ===========================================================================
// Tensor-core primitives (baseline PTX — valid on compute_103 non-'a')
// ===========================================================================
__device__ __forceinline__ uint32_t smem_u32(const void* p) {
    uint32_t a;
    asm("{ .reg .u64 t; cvta.to.shared.u64 t, %1; cvt.u32.u64 %0, t; }"
        : "=r"(a) : "l"(p));
    return a;
}
__device__ __forceinline__ void ldm4(uint32_t addr,
    uint32_t& r0, uint32_t& r1, uint32_t& r2, uint32_t& r3)
{
    asm volatile("ldmatrix.sync.aligned.m8n8.x4.shared.b16 {%0,%1,%2,%3}, [%4];"
                 : "=r"(r0), "=r"(r1), "=r"(r2), "=r"(r3) : "r"(addr));
}
__device__ __forceinline__ void mma16816(float* d,
    uint32_t a0, uint32_t a1, uint32_t a2, uint32_t a3,
    uint32_t b0, uint32_t b1)
{
    asm volatile(
        "mma.sync.aligned.m16n8k16.row.col.f32.bf16.bf16.f32 "
        "{%0,%1,%2,%3}, {%4,%5,%6,%7}, {%8,%9}, {%0,%1,%2,%3};"
        : "+f"(d[0]), "+f"(d[1]), "+f"(d[2]), "+f"(d[3])
        : "r"(a0), "r"(a1), "r"(a2), "r"(a3), "r"(b0), "r"(b1));
}
__device__ __forceinline__ void split4(float4 v, uint2& hi, uint2& lo) {
    __nv_bfloat16 h0 = __float2bfloat16(v.x);
    __nv_bfloat16 h1 = __float2bfloat16(v.y);
    __nv_bfloat16 h2 = __float2bfloat16(v.z);
    __nv_bfloat16 h3 = __float2bfloat16(v.w);
    __nv_bfloat16 l0 = __float2bfloat16(v.x - __bfloat162float(h0));
    __nv_bfloat16 l1 = __float2bfloat16(v.y - __bfloat162float(h1));
    __nv_bfloat16 l2 = __float2bfloat16(v.z - __bfloat162float(h2));
    __nv_bfloat16 l3 = __float2bfloat16(v.w - __bfloat162float(h3));
    hi.x = (uint32_t)__bfloat16_as_ushort(h0) | ((uint32_t)__bfloat16_as_ushort(h1) << 16);
    hi.y = (uint32_t)__bfloat16_as_ushort(h2) | ((uint32_t)__bfloat16_as_ushort(h3) << 16);
    lo.x = (uint32_t)__bfloat16_as_ushort(l0) | ((uint32_t)__bfloat16_as_ushort(l1) << 16);
    lo.y = (uint32_t)__bfloat16_as_ushort(l2) | ((uint32_t)__bfloat16_as_ushort(l3) << 16);
}

// ===========================================================================
// Fused: y = x @ W^T + b, inverted dropout (keep=0.8), bf16 hi/lo split GEMM
// (HH + LH + HL). Dropout keep-bits are computed as a 64-bit per-thread
// bitmask INTERLEAVED into the k-loop so RNG issue fills GEMM stall slots.
//
// Block 128x128, 256 threads = 8 warps, warp tile 32x64. Smem rows padded to
// 80B. Templated on KSTEPS = C/32.
// ===========================================================================
#define RS 40   // smem row stride in bf16 elems (80 bytes)

template<int KSTEPS>
__global__ __launch_bounds__(256, 2) void fused_gemm_dropout(
    const float* __restrict__ x, const float* __restrict__ W,
    const float* __restrict__ bias, float* __restrict__ out,
    int N, uint32_t k0, uint32_t k1)
{
    constexpr int C   = KSTEPS * 32;
    constexpr int MPT = (64 + KSTEPS - 1) / KSTEPS;   // masks per k-tile

    __shared__ __align__(16) uint16_t Ah[128 * RS], Al[128 * RS];
    __shared__ __align__(16) uint16_t Bh[128 * RS], Bl[128 * RS];

    const int tid  = threadIdx.x;
    const int lane = tid & 31;
    const int warp = tid >> 5;
    const int wm   = warp & 3;
    const int wn   = warp >> 2;
    const int base = blockIdx.x * 128;

    const uint32_t uAh = smem_u32(Ah), uAl = smem_u32(Al);
    const uint32_t uBh = smem_u32(Bh), uBl = smem_u32(Bl);

    const int r16  = lane & 15;
    const int hc16 = (lane >> 4) << 4;
    const int rowq = lane >> 2;
    const int colq = (lane & 3) * 2;
    const uint32_t ks2 = k0 ^ k1 ^ 0x1BD11BDAu;

    float acc[2][8][4];
#pragma unroll
    for (int i = 0; i < 2; i++)
#pragma unroll
        for (int j = 0; j < 8; j++)
#pragma unroll
            for (int q = 0; q < 4; q++) acc[i][j][q] = 0.0f;

    uint32_t kmask0 = 0, kmask1 = 0;

    for (int kt = 0; kt < KSTEPS; kt++) {
        const int kb = kt * 32;
        // ---- load fp32, split to bf16 hi/lo, store to smem ----
#pragma unroll
        for (int it = 0; it < 4; it++) {
            int idx = tid + it * 256;
            int row = idx >> 3;
            int q   = idx & 7;
            int soff = row * RS + q * 4;

            int gr = base + row;
            float4 va = make_float4(0.f, 0.f, 0.f, 0.f);
            if (gr < N) va = *(const float4*)(x + (long)gr * C + kb + q * 4);
            uint2 hi, lo;
            split4(va, hi, lo);
            *(uint2*)(Ah + soff) = hi;
            *(uint2*)(Al + soff) = lo;

            float4 vw = *(const float4*)(W + (long)row * C + kb + q * 4);
            split4(vw, hi, lo);
            *(uint2*)(Bh + soff) = hi;
            *(uint2*)(Bl + soff) = lo;
        }
        __syncthreads();

        // ---- interleaved dropout-mask chunk (indices kt*MPT .. ) ----
#pragma unroll
        for (int ii = 0; ii < MPT; ii++) {
            int i = kt * MPT + ii;
            if (i < 64) {
                int am = i >> 5, an = (i >> 2) & 7, rp = (i >> 1) & 1, cp = i & 1;
                uint32_t row = (uint32_t)(base + wm * 32 + am * 16 + rowq + rp * 8);
                uint32_t col = (uint32_t)(wn * 64 + an * 8 + colq + cp);
                uint32_t keep = tf_keep(k0, k1, ks2, row * 128u + col);
                if (i < 32) kmask0 |= keep << i;
                else        kmask1 |= keep << (i - 32);
            }
        }

        // ---- MMA: 2 k16 chunks, HH + LH + HL ----
#pragma unroll
        for (int c = 0; c < 2; c++) {
            const int coff = c * 32 + hc16;

            uint32_t ah[2][4];
#pragma unroll
            for (int am = 0; am < 2; am++)
                ldm4(uAh + (uint32_t)((wm * 32 + am * 16 + r16) * 80 + coff),
                     ah[am][0], ah[am][1], ah[am][2], ah[am][3]);

            uint32_t b[4][4];
#pragma unroll
            for (int p = 0; p < 4; p++)
                ldm4(uBh + (uint32_t)((wn * 64 + p * 16 + r16) * 80 + coff),
                     b[p][0], b[p][1], b[p][2], b[p][3]);

#pragma unroll
            for (int am = 0; am < 2; am++)
#pragma unroll
                for (int p = 0; p < 4; p++) {
                    mma16816(acc[am][2 * p],     ah[am][0], ah[am][1], ah[am][2], ah[am][3], b[p][0], b[p][2]);
                    mma16816(acc[am][2 * p + 1], ah[am][0], ah[am][1], ah[am][2], ah[am][3], b[p][1], b[p][3]);
                }

            uint32_t al[2][4];
#pragma unroll
            for (int am = 0; am < 2; am++)
                ldm4(uAl + (uint32_t)((wm * 32 + am * 16 + r16) * 80 + coff),
                     al[am][0], al[am][1], al[am][2], al[am][3]);
#pragma unroll
            for (int am = 0; am < 2; am++)
#pragma unroll
                for (int p = 0; p < 4; p++) {
                    mma16816(acc[am][2 * p],     al[am][0], al[am][1], al[am][2], al[am][3], b[p][0], b[p][2]);
                    mma16816(acc[am][2 * p + 1], al[am][0], al[am][1], al[am][2], al[am][3], b[p][1], b[p][3]);
                }

#pragma unroll
            for (int p = 0; p < 4; p++)
                ldm4(uBl + (uint32_t)((wn * 64 + p * 16 + r16) * 80 + coff),
                     b[p][0], b[p][1], b[p][2], b[p][3]);
#pragma unroll
            for (int am = 0; am < 2; am++)
#pragma unroll
                for (int p = 0; p < 4; p++) {
                    mma16816(acc[am][2 * p],     ah[am][0], ah[am][1], ah[am][2], ah[am][3], b[p][0], b[p][2]);
                    mma16816(acc[am][2 * p + 1], ah[am][0], ah[am][1], ah[am][2], ah[am][3], b[p][1], b[p][3]);
                }
        }
        __syncthreads();
    }

    // ---- epilogue: bias + masked scale + store (mask bit i matches order) ----
#pragma unroll
    for (int am = 0; am < 2; am++) {
        int row0 = base + wm * 32 + am * 16 + rowq;
#pragma unroll
        for (int an = 0; an < 8; an++) {
            int col = wn * 64 + an * 8 + colq;
            float b0 = __ldg(bias + col);
            float b1 = __ldg(bias + col + 1);
            int ibase = ((am * 8 + an) << 2);    // i = ibase + rp*2 + cp
#pragma unroll
            for (int rp = 0; rp < 2; rp++) {
                int row = row0 + rp * 8;
                if (row < N) {
                    int i0 = ibase + rp * 2;
                    uint32_t m = (am == 0) ? kmask0 : kmask1;
                    uint32_t bit0 = (m >> (i0 & 31)) & 1u;
                    uint32_t bit1 = (m >> ((i0 + 1) & 31)) & 1u;
                    float y0 = acc[am][an][rp * 2 + 0] + b0;
                    float y1 = acc[am][an][rp * 2 + 1] + b1;
                    float2 v;
                    v.x = bit0 ? y0 * 1.25f : 0.0f;
                    v.y = bit1 ? y1 * 1.25f : 0.0f;
                    *(float2*)(out + (size_t)row * 128 + col) = v;
                }
            }
        }
    }
}

// ===========================================================================
// Launch: 8 fused kernels. Inputs interleaved (x_t, W_t, b_t) x 8; detect.
// ===========================================================================
static const int C_TAB[8] = {128, 256, 64, 128, 192, 96, 160, 128};

typedef void (*KFn)(const float*, const float*, const float*, float*, int, uint32_t, uint32_t);

extern "C" void kernel_launch(void* const* d_in, const int* in_sizes, int n_in,
                              void* d_out, int out_size)
{
    (void)n_in; (void)out_size;
    const bool interleaved = (in_sizes[1] == 128 * C_TAB[0]);

    size_t off = 0;
    for (int t = 0; t < 8; t++) {
        const int C = C_TAB[t];
        const int xi = interleaved ? (3 * t)     : t;
        const int wi = interleaved ? (3 * t + 1) : (8 + t);
        const int bi = interleaved ? (3 * t + 2) : (16 + t);
        const int N  = in_sizes[xi] / C;

        uint32_t fk0, fk1;
        threefry2x32_host(0u, 42u, 0u, (uint32_t)t, fk0, fk1);

        const float* x = (const float*)d_in[xi];
        const float* W = (const float*)d_in[wi];
        const float* b = (const float*)d_in[bi];
        float* out = (float*)d_out + off;

        KFn fn = nullptr;
        switch (C) {
            case 64:  fn = fused_gemm_dropout<2>; break;
            case 96:  fn = fused_gemm_dropout<3>; break;
            case 128: fn = fused_gemm_dropout<4>; break;
            case 160: fn = fused_gemm_dropout<5>; break;
            case 192: fn = fused_gemm_dropout<6>; break;
            case 256: fn = fused_gemm_dropout<8>; break;
        }
        int grid = (N + 127) / 128;
        fn<<<grid, 256>>>(x, W, b, out, N, fk0, fk1);

        off += (size_t)N * 128;
    }
}

// round 10
// speedup vs baseline: 1.2871x; 1.2871x over previous
#include <cuda_runtime.h>
#include <cuda_bf16.h>
#include <stdint.h>

// ===========================================================================
// JAX threefry2x32 (exact)
// ===========================================================================
static void threefry2x32_host(
    uint32_t k0, uint32_t k1, uint32_t x0, uint32_t x1,
    uint32_t& o0, uint32_t& o1)
{
    uint32_t ks2 = k0 ^ k1 ^ 0x1BD11BDAu;
    x0 += k0; x1 += k1;
#define TF_RNDH(R) { x0 += x1; x1 = (x1 << (R)) | (x1 >> (32 - (R))); x1 ^= x0; }
    TF_RNDH(13) TF_RNDH(15) TF_RNDH(26) TF_RNDH(6)   x0 += k1;  x1 += ks2 + 1u;
    TF_RNDH(17) TF_RNDH(29) TF_RNDH(16) TF_RNDH(24)  x0 += ks2; x1 += k0  + 2u;
    TF_RNDH(13) TF_RNDH(15) TF_RNDH(26) TF_RNDH(6)   x0 += k0;  x1 += k1  + 3u;
    TF_RNDH(17) TF_RNDH(29) TF_RNDH(16) TF_RNDH(24)  x0 += k1;  x1 += ks2 + 4u;
    TF_RNDH(13) TF_RNDH(15) TF_RNDH(26) TF_RNDH(6)   x0 += ks2; x1 += k0  + 5u;
#undef TF_RNDH
    o0 = x0; o1 = x1;
}

// keep-decision for flat element e: partitionable threefry counter (0, e),
// XOR-fold, uniform<0.8f as EXACT integer compare:
//   m = bits>>9; u = m*2^-23; 0.8f = 6710886.5*2^-23
//   u < 0.8f  <=>  m <= 0x666666  <=>  bits < 0xCCCCCE00   (verified R9)
__device__ __forceinline__ uint32_t tf_keep(uint32_t k0, uint32_t k1, uint32_t ks2,
                                            uint32_t e)
{
    uint32_t x0 = k0, x1 = e + k1;
#define TF_RND(R) { x0 += x1; x1 = __funnelshift_l(x1, x1, R); x1 ^= x0; }
    TF_RND(13) TF_RND(15) TF_RND(26) TF_RND(6)   x0 += k1;  x1 += ks2 + 1u;
    TF_RND(17) TF_RND(29) TF_RND(16) TF_RND(24)  x0 += ks2; x1 += k0  + 2u;
    TF_RND(13) TF_RND(15) TF_RND(26) TF_RND(6)   x0 += k0;  x1 += k1  + 3u;
    TF_RND(17) TF_RND(29) TF_RND(16) TF_RND(24)  x0 += k1;  x1 += ks2 + 4u;
    TF_RND(13) TF_RND(15) TF_RND(26) TF_RND(6)   x0 += ks2; x1 += k0  + 5u;
#undef TF_RND
    return ((x0 ^ x1) < 0xCCCCCE00u) ? 1u : 0u;
}

// ===========================================================================
// Tensor-core primitives (baseline PTX — valid on compute_103 non-'a')
// ===========================================================================
__device__ __forceinline__ uint32_t smem_u32(const void* p) {
    uint32_t a;
    asm("{ .reg .u64 t; cvta.to.shared.u64 t, %1; cvt.u32.u64 %0, t; }"
        : "=r"(a) : "l"(p));
    return a;
}
__device__ __forceinline__ void ldm4(uint32_t addr,
    uint32_t& r0, uint32_t& r1, uint32_t& r2, uint32_t& r3)
{
    asm volatile("ldmatrix.sync.aligned.m8n8.x4.shared.b16 {%0,%1,%2,%3}, [%4];"
                 : "=r"(r0), "=r"(r1), "=r"(r2), "=r"(r3) : "r"(addr));
}
__device__ __forceinline__ void mma16816(float* d,
    uint32_t a0, uint32_t a1, uint32_t a2, uint32_t a3,
    uint32_t b0, uint32_t b1)
{
    asm volatile(
        "mma.sync.aligned.m16n8k16.row.col.f32.bf16.bf16.f32 "
        "{%0,%1,%2,%3}, {%4,%5,%6,%7}, {%8,%9}, {%0,%1,%2,%3};"
        : "+f"(d[0]), "+f"(d[1]), "+f"(d[2]), "+f"(d[3])
        : "r"(a0), "r"(a1), "r"(a2), "r"(a3), "r"(b0), "r"(b1));
}
__device__ __forceinline__ void split4(float4 v, uint2& hi, uint2& lo) {
    __nv_bfloat16 h0 = __float2bfloat16(v.x);
    __nv_bfloat16 h1 = __float2bfloat16(v.y);
    __nv_bfloat16 h2 = __float2bfloat16(v.z);
    __nv_bfloat16 h3 = __float2bfloat16(v.w);
    __nv_bfloat16 l0 = __float2bfloat16(v.x - __bfloat162float(h0));
    __nv_bfloat16 l1 = __float2bfloat16(v.y - __bfloat162float(h1));
    __nv_bfloat16 l2 = __float2bfloat16(v.z - __bfloat162float(h2));
    __nv_bfloat16 l3 = __float2bfloat16(v.w - __bfloat162float(h3));
    hi.x = (uint32_t)__bfloat16_as_ushort(h0) | ((uint32_t)__bfloat16_as_ushort(h1) << 16);
    hi.y = (uint32_t)__bfloat16_as_ushort(h2) | ((uint32_t)__bfloat16_as_ushort(h3) << 16);
    lo.x = (uint32_t)__bfloat16_as_ushort(l0) | ((uint32_t)__bfloat16_as_ushort(l1) << 16);
    lo.y = (uint32_t)__bfloat16_as_ushort(l2) | ((uint32_t)__bfloat16_as_ushort(l3) << 16);
}

// ===========================================================================
// Grouped fused kernel: ALL 8 types in ONE launch.
// Block 128x128, 256 threads = 8 warps, warp tile 32x64. bf16 hi/lo split
// GEMM (HH+LH+HL) + bias + partitionable-threefry inverted dropout.
// 64 mask bits per thread computed in 2 unrolled chunks of 32 overlapped
// with k-tiles 0 and 1 (all C >= 64 so both exist).
// ===========================================================================
#define RS 40   // smem row stride in bf16 elems (80 bytes)

struct Entry {
    const float* x;
    const float* W;
    const float* bias;
    float*       out;
    int N, C, ksteps, bstart;
    uint32_t k0, k1;
};
struct Params { Entry e[8]; };

__global__ __launch_bounds__(256, 2) void fused_all(Params p)
{
    __shared__ __align__(16) uint16_t Ah[128 * RS], Al[128 * RS];
    __shared__ __align__(16) uint16_t Bh[128 * RS], Bl[128 * RS];

    const int bid = blockIdx.x;
    int t = 0;
#pragma unroll
    for (int i = 1; i < 8; i++)
        if (bid >= p.e[i].bstart) t = i;

    const float* __restrict__ x    = p.e[t].x;
    const float* __restrict__ W    = p.e[t].W;
    const float* __restrict__ bias = p.e[t].bias;
    float*       __restrict__ out  = p.e[t].out;
    const int N      = p.e[t].N;
    const int C      = p.e[t].C;
    const int ksteps = p.e[t].ksteps;
    const uint32_t k0 = p.e[t].k0, k1 = p.e[t].k1;
    const uint32_t ks2 = k0 ^ k1 ^ 0x1BD11BDAu;
    const int base = (bid - p.e[t].bstart) * 128;

    const int tid  = threadIdx.x;
    const int lane = tid & 31;
    const int warp = tid >> 5;
    const int wm   = warp & 3;
    const int wn   = warp >> 2;

    const uint32_t uAh = smem_u32(Ah), uAl = smem_u32(Al);
    const uint32_t uBh = smem_u32(Bh), uBl = smem_u32(Bl);

    const int r16  = lane & 15;
    const int hc16 = (lane >> 4) << 4;
    const int rowq = lane >> 2;
    const int colq = (lane & 3) * 2;

    float acc[2][8][4];
#pragma unroll
    for (int i = 0; i < 2; i++)
#pragma unroll
        for (int j = 0; j < 8; j++)
#pragma unroll
            for (int q = 0; q < 4; q++) acc[i][j][q] = 0.0f;

    uint32_t kmask0 = 0, kmask1 = 0;

    for (int kt = 0; kt < ksteps; kt++) {
        const int kb = kt * 32;
        // ---- load fp32, split to bf16 hi/lo, store to smem ----
#pragma unroll
        for (int it = 0; it < 4; it++) {
            int idx = tid + it * 256;
            int row = idx >> 3;
            int q   = idx & 7;
            int soff = row * RS + q * 4;

            int gr = base + row;
            float4 va = make_float4(0.f, 0.f, 0.f, 0.f);
            if (gr < N) va = *(const float4*)(x + (long)gr * C + kb + q * 4);
            uint2 hi, lo;
            split4(va, hi, lo);
            *(uint2*)(Ah + soff) = hi;
            *(uint2*)(Al + soff) = lo;

            float4 vw = *(const float4*)(W + (long)row * C + kb + q * 4);
            split4(vw, hi, lo);
            *(uint2*)(Bh + soff) = hi;
            *(uint2*)(Bl + soff) = lo;
        }
        __syncthreads();

        // ---- dropout mask chunk: 32 keep-bits in tiles 0 and 1 ----
        // bit ii of kmask[kt]: an=(ii>>2)&7, rp=(ii>>1)&1, cp=ii&1,
        // m-group = kt (16-row group), matching epilogue's i=(am*8+an)*4+rp*2+cp
        if (kt < 2) {
            uint32_t m = 0;
#pragma unroll
            for (int ii = 0; ii < 32; ii++) {
                int an = (ii >> 2) & 7, rp = (ii >> 1) & 1, cp = ii & 1;
                uint32_t row = (uint32_t)(base + wm * 32 + kt * 16 + rowq + rp * 8);
                uint32_t col = (uint32_t)(wn * 64 + an * 8 + colq + cp);
                m |= tf_keep(k0, k1, ks2, row * 128u + col) << ii;
            }
            if (kt == 0) kmask0 = m; else kmask1 = m;
        }

        // ---- MMA: 2 k16 chunks, HH + LH + HL ----
#pragma unroll
        for (int c = 0; c < 2; c++) {
            const int coff = c * 32 + hc16;

            uint32_t ah[2][4];
#pragma unroll
            for (int am = 0; am < 2; am++)
                ldm4(uAh + (uint32_t)((wm * 32 + am * 16 + r16) * 80 + coff),
                     ah[am][0], ah[am][1], ah[am][2], ah[am][3]);

            uint32_t b[4][4];
#pragma unroll
            for (int pgi = 0; pgi < 4; pgi++)
                ldm4(uBh + (uint32_t)((wn * 64 + pgi * 16 + r16) * 80 + coff),
                     b[pgi][0], b[pgi][1], b[pgi][2], b[pgi][3]);

#pragma unroll
            for (int am = 0; am < 2; am++)
#pragma unroll
                for (int pgi = 0; pgi < 4; pgi++) {
                    mma16816(acc[am][2 * pgi],     ah[am][0], ah[am][1], ah[am][2], ah[am][3], b[pgi][0], b[pgi][2]);
                    mma16816(acc[am][2 * pgi + 1], ah[am][0], ah[am][1], ah[am][2], ah[am][3], b[pgi][1], b[pgi][3]);
                }

            uint32_t al[2][4];
#pragma unroll
            for (int am = 0; am < 2; am++)
                ldm4(uAl + (uint32_t)((wm * 32 + am * 16 + r16) * 80 + coff),
                     al[am][0], al[am][1], al[am][2], al[am][3]);
#pragma unroll
            for (int am = 0; am < 2; am++)
#pragma unroll
                for (int pgi = 0; pgi < 4; pgi++) {
                    mma16816(acc[am][2 * pgi],     al[am][0], al[am][1], al[am][2], al[am][3], b[pgi][0], b[pgi][2]);
                    mma16816(acc[am][2 * pgi + 1], al[am][0], al[am][1], al[am][2], al[am][3], b[pgi][1], b[pgi][3]);
                }

#pragma unroll
            for (int pgi = 0; pgi < 4; pgi++)
                ldm4(uBl + (uint32_t)((wn * 64 + pgi * 16 + r16) * 80 + coff),
                     b[pgi][0], b[pgi][1], b[pgi][2], b[pgi][3]);
#pragma unroll
            for (int am = 0; am < 2; am++)
#pragma unroll
                for (int pgi = 0; pgi < 4; pgi++) {
                    mma16816(acc[am][2 * pgi],     ah[am][0], ah[am][1], ah[am][2], ah[am][3], b[pgi][0], b[pgi][2]);
                    mma16816(acc[am][2 * pgi + 1], ah[am][0], ah[am][1], ah[am][2], ah[am][3], b[pgi][1], b[pgi][3]);
                }
        }
        __syncthreads();
    }

    // ---- epilogue: bias + masked scale + store ----
#pragma unroll
    for (int am = 0; am < 2; am++) {
        int row0 = base + wm * 32 + am * 16 + rowq;
        uint32_t m = (am == 0) ? kmask0 : kmask1;
#pragma unroll
        for (int an = 0; an < 8; an++) {
            int col = wn * 64 + an * 8 + colq;
            float b0 = __ldg(bias + col);
            float b1 = __ldg(bias + col + 1);
#pragma unroll
            for (int rp = 0; rp < 2; rp++) {
                int row = row0 + rp * 8;
                if (row < N) {
                    int i0 = an * 4 + rp * 2;
                    uint32_t bit0 = (m >> i0) & 1u;
                    uint32_t bit1 = (m >> (i0 + 1)) & 1u;
                    float y0 = acc[am][an][rp * 2 + 0] + b0;
                    float y1 = acc[am][an][rp * 2 + 1] + b1;
                    float2 v;
                    v.x = bit0 ? y0 * 1.25f : 0.0f;
                    v.y = bit1 ? y1 * 1.25f : 0.0f;
                    *(float2*)(out + (size_t)row * 128 + col) = v;
                }
            }
        }
    }
}

// ===========================================================================
// Launch: ONE grouped kernel. Inputs interleaved (x_t, W_t, b_t) x 8; detect.
// ===========================================================================
static const int C_TAB[8] = {128, 256, 64, 128, 192, 96, 160, 128};

extern "C" void kernel_launch(void* const* d_in, const int* in_sizes, int n_in,
                              void* d_out, int out_size)
{
    (void)n_in; (void)out_size;
    const bool interleaved = (in_sizes[1] == 128 * C_TAB[0]);

    Params p;
    size_t off = 0;
    int bstart = 0;
    for (int t = 0; t < 8; t++) {
        const int C = C_TAB[t];
        const int xi = interleaved ? (3 * t)     : t;
        const int wi = interleaved ? (3 * t + 1) : (8 + t);
        const int bi = interleaved ? (3 * t + 2) : (16 + t);
        const int N  = in_sizes[xi] / C;

        uint32_t fk0, fk1;
        threefry2x32_host(0u, 42u, 0u, (uint32_t)t, fk0, fk1);

        p.e[t].x      = (const float*)d_in[xi];
        p.e[t].W      = (const float*)d_in[wi];
        p.e[t].bias   = (const float*)d_in[bi];
        p.e[t].out    = (float*)d_out + off;
        p.e[t].N      = N;
        p.e[t].C      = C;
        p.e[t].ksteps = C / 32;
        p.e[t].bstart = bstart;
        p.e[t].k0     = fk0;
        p.e[t].k1     = fk1;

        bstart += (N + 127) / 128;
        off += (size_t)N * 128;
    }

    fused_all<<<bstart, 256>>>(p);
}

// round 11
// speedup vs baseline: 1.4744x; 1.1455x over previous
#include <cuda_runtime.h>
#include <stdint.h>

// ===========================================================================
// JAX threefry2x32 (exact)
// ===========================================================================
static void threefry2x32_host(
    uint32_t k0, uint32_t k1, uint32_t x0, uint32_t x1,
    uint32_t& o0, uint32_t& o1)
{
    uint32_t ks2 = k0 ^ k1 ^ 0x1BD11BDAu;
    x0 += k0; x1 += k1;
#define TF_RNDH(R) { x0 += x1; x1 = (x1 << (R)) | (x1 >> (32 - (R))); x1 ^= x0; }
    TF_RNDH(13) TF_RNDH(15) TF_RNDH(26) TF_RNDH(6)   x0 += k1;  x1 += ks2 + 1u;
    TF_RNDH(17) TF_RNDH(29) TF_RNDH(16) TF_RNDH(24)  x0 += ks2; x1 += k0  + 2u;
    TF_RNDH(13) TF_RNDH(15) TF_RNDH(26) TF_RNDH(6)   x0 += k0;  x1 += k1  + 3u;
    TF_RNDH(17) TF_RNDH(29) TF_RNDH(16) TF_RNDH(24)  x0 += k1;  x1 += ks2 + 4u;
    TF_RNDH(13) TF_RNDH(15) TF_RNDH(26) TF_RNDH(6)   x0 += ks2; x1 += k0  + 5u;
#undef TF_RNDH
    o0 = x0; o1 = x1;
}

// keep-decision for flat element e: partitionable threefry counter (0, e),
// XOR-fold, uniform<0.8f as EXACT integer compare: bits < 0xCCCCCE00 (R9-verified)
__device__ __forceinline__ uint32_t tf_keep(uint32_t k0, uint32_t k1, uint32_t ks2,
                                            uint32_t e)
{
    uint32_t x0 = k0, x1 = e + k1;
#define TF_RND(R) { x0 += x1; x1 = __funnelshift_l(x1, x1, R); x1 ^= x0; }
    TF_RND(13) TF_RND(15) TF_RND(26) TF_RND(6)   x0 += k1;  x1 += ks2 + 1u;
    TF_RND(17) TF_RND(29) TF_RND(16) TF_RND(24)  x0 += ks2; x1 += k0  + 2u;
    TF_RND(13) TF_RND(15) TF_RND(26) TF_RND(6)   x0 += k0;  x1 += k1  + 3u;
    TF_RND(17) TF_RND(29) TF_RND(16) TF_RND(24)  x0 += k1;  x1 += ks2 + 4u;
    TF_RND(13) TF_RND(15) TF_RND(26) TF_RND(6)   x0 += ks2; x1 += k0  + 5u;
#undef TF_RND
    return ((x0 ^ x1) < 0xCCCCCE00u) ? 1u : 0u;
}

// ===========================================================================
// Tensor-core primitives (baseline PTX — valid on compute_103 non-'a')
// ===========================================================================
__device__ __forceinline__ uint32_t smem_u32(const void* p) {
    uint32_t a;
    asm("{ .reg .u64 t; cvta.to.shared.u64 t, %1; cvt.u32.u64 %0, t; }"
        : "=r"(a) : "l"(p));
    return a;
}
__device__ __forceinline__ void ldm4(uint32_t addr,
    uint32_t& r0, uint32_t& r1, uint32_t& r2, uint32_t& r3)
{
    asm volatile("ldmatrix.sync.aligned.m8n8.x4.shared.b16 {%0,%1,%2,%3}, [%4];"
                 : "=r"(r0), "=r"(r1), "=r"(r2), "=r"(r3) : "r"(addr));
}
// tf32 m16n8k8: A = 4 b32 regs, B = 2 b32 regs, fp32 accum.
// Fragment layouts are the fp32-word view of the bf16 m16n8k16 layouts, so
// the ldmatrix.b16 addressing pattern carries over unchanged.
__device__ __forceinline__ void mma1688(float* d,
    uint32_t a0, uint32_t a1, uint32_t a2, uint32_t a3,
    uint32_t b0, uint32_t b1)
{
    asm volatile(
        "mma.sync.aligned.m16n8k8.row.col.f32.tf32.tf32.f32 "
        "{%0,%1,%2,%3}, {%4,%5,%6,%7}, {%8,%9}, {%0,%1,%2,%3};"
        : "+f"(d[0]), "+f"(d[1]), "+f"(d[2]), "+f"(d[3])
        : "r"(a0), "r"(a1), "r"(a2), "r"(a3), "r"(b0), "r"(b1));
}
// fp32 -> tf32 with round-to-nearest (RNA). Unbiased: truncation would give a
// coherent ~2^-11-per-operand bias (~1e-3 on the sum) — must round.
__device__ __forceinline__ uint32_t f2tf32(float f) {
    uint32_t u;
    asm("cvt.rna.tf32.f32 %0, %1;" : "=r"(u) : "f"(f));
    return u;
}
__device__ __forceinline__ uint4 cvt4(float4 v) {
    return make_uint4(f2tf32(v.x), f2tf32(v.y), f2tf32(v.z), f2tf32(v.w));
}

// ===========================================================================
// Grouped fused kernel: ALL 8 types in ONE launch.
// Block 128x128, 256 threads = 8 warps, warp tile 32x64.
// tf32 single-product GEMM + bias + partitionable-threefry inverted dropout.
// Smem tiles are raw fp32 (tf32-rounded) [128][36] (pad 36 words -> 144B rows,
// conflict-free ldmatrix). 64 mask bits per thread computed in 2 chunks of 32
// overlapped with k-tiles 0 and 1 (all C >= 64).
// ===========================================================================
#define RSW 36   // smem row stride in fp32 words (144 bytes)

struct Entry {
    const float* x;
    const float* W;
    const float* bias;
    float*       out;
    int N, C, ksteps, bstart;
    uint32_t k0, k1;
};
struct Params { Entry e[8]; };

__global__ __launch_bounds__(256, 2) void fused_all(Params p)
{
    __shared__ __align__(16) uint32_t Asm[128 * RSW];
    __shared__ __align__(16) uint32_t Bsm[128 * RSW];

    const int bid = blockIdx.x;
    int t = 0;
#pragma unroll
    for (int i = 1; i < 8; i++)
        if (bid >= p.e[i].bstart) t = i;

    const float* __restrict__ x    = p.e[t].x;
    const float* __restrict__ W    = p.e[t].W;
    const float* __restrict__ bias = p.e[t].bias;
    float*       __restrict__ out  = p.e[t].out;
    const int N      = p.e[t].N;
    const int C      = p.e[t].C;
    const int ksteps = p.e[t].ksteps;
    const uint32_t k0 = p.e[t].k0, k1 = p.e[t].k1;
    const uint32_t ks2 = k0 ^ k1 ^ 0x1BD11BDAu;
    const int base = (bid - p.e[t].bstart) * 128;

    const int tid  = threadIdx.x;
    const int lane = tid & 31;
    const int warp = tid >> 5;
    const int wm   = warp & 3;
    const int wn   = warp >> 2;

    const uint32_t uA = smem_u32(Asm), uB = smem_u32(Bsm);

    const int r16  = lane & 15;
    const int hc16 = (lane >> 4) << 4;   // 0 or 16 bytes (4-fp32 col half)
    const int rowq = lane >> 2;
    const int colq = (lane & 3) * 2;

    float acc[2][8][4];
#pragma unroll
    for (int i = 0; i < 2; i++)
#pragma unroll
        for (int j = 0; j < 8; j++)
#pragma unroll
            for (int q = 0; q < 4; q++) acc[i][j][q] = 0.0f;

    uint32_t kmask0 = 0, kmask1 = 0;

    for (int kt = 0; kt < ksteps; kt++) {
        const int kb = kt * 32;
        // ---- load fp32, tf32-round, store to smem ----
#pragma unroll
        for (int it = 0; it < 4; it++) {
            int idx = tid + it * 256;     // 0..1023
            int row = idx >> 3;           // 0..127
            int q   = idx & 7;            // float4 group
            int soff = row * RSW + q * 4;

            int gr = base + row;
            float4 va = make_float4(0.f, 0.f, 0.f, 0.f);
            if (gr < N) va = *(const float4*)(x + (long)gr * C + kb + q * 4);
            *(uint4*)(Asm + soff) = cvt4(va);

            float4 vw = *(const float4*)(W + (long)row * C + kb + q * 4);
            *(uint4*)(Bsm + soff) = cvt4(vw);
        }
        __syncthreads();

        // ---- dropout mask chunk: 32 keep-bits in tiles 0 and 1 ----
        if (kt < 2) {
            uint32_t m = 0;
#pragma unroll
            for (int ii = 0; ii < 32; ii++) {
                int an = (ii >> 2) & 7, rp = (ii >> 1) & 1, cp = ii & 1;
                uint32_t row = (uint32_t)(base + wm * 32 + kt * 16 + rowq + rp * 8);
                uint32_t col = (uint32_t)(wn * 64 + an * 8 + colq + cp);
                m |= tf_keep(k0, k1, ks2, row * 128u + col) << ii;
            }
            if (kt == 0) kmask0 = m; else kmask1 = m;
        }

        // ---- MMA: 4 chunks of 8 fp32-k ----
#pragma unroll
        for (int c8 = 0; c8 < 4; c8++) {
            const int coff = c8 * 32 + hc16;

            uint32_t ah[2][4];
#pragma unroll
            for (int am = 0; am < 2; am++)
                ldm4(uA + (uint32_t)((wm * 32 + am * 16 + r16) * 144 + coff),
                     ah[am][0], ah[am][1], ah[am][2], ah[am][3]);

            uint32_t b[4][4];
#pragma unroll
            for (int pg = 0; pg < 4; pg++)
                ldm4(uB + (uint32_t)((wn * 64 + pg * 16 + r16) * 144 + coff),
                     b[pg][0], b[pg][1], b[pg][2], b[pg][3]);

#pragma unroll
            for (int am = 0; am < 2; am++)
#pragma unroll
                for (int pg = 0; pg < 4; pg++) {
                    mma1688(acc[am][2 * pg],     ah[am][0], ah[am][1], ah[am][2], ah[am][3], b[pg][0], b[pg][2]);
                    mma1688(acc[am][2 * pg + 1], ah[am][0], ah[am][1], ah[am][2], ah[am][3], b[pg][1], b[pg][3]);
                }
        }
        __syncthreads();
    }

    // ---- epilogue: bias + masked scale + store ----
#pragma unroll
    for (int am = 0; am < 2; am++) {
        int row0 = base + wm * 32 + am * 16 + rowq;
        uint32_t m = (am == 0) ? kmask0 : kmask1;
#pragma unroll
        for (int an = 0; an < 8; an++) {
            int col = wn * 64 + an * 8 + colq;
            float b0 = __ldg(bias + col);
            float b1 = __ldg(bias + col + 1);
#pragma unroll
            for (int rp = 0; rp < 2; rp++) {
                int row = row0 + rp * 8;
                if (row < N) {
                    int i0 = an * 4 + rp * 2;
                    uint32_t bit0 = (m >> i0) & 1u;
                    uint32_t bit1 = (m >> (i0 + 1)) & 1u;
                    float y0 = acc[am][an][rp * 2 + 0] + b0;
                    float y1 = acc[am][an][rp * 2 + 1] + b1;
                    float2 v;
                    v.x = bit0 ? y0 * 1.25f : 0.0f;
                    v.y = bit1 ? y1 * 1.25f : 0.0f;
                    *(float2*)(out + (size_t)row * 128 + col) = v;
                }
            }
        }
    }
}

// ===========================================================================
// Launch: ONE grouped kernel. Inputs interleaved (x_t, W_t, b_t) x 8; detect.
// ===========================================================================
static const int C_TAB[8] = {128, 256, 64, 128, 192, 96, 160, 128};

extern "C" void kernel_launch(void* const* d_in, const int* in_sizes, int n_in,
                              void* d_out, int out_size)
{
    (void)n_in; (void)out_size;
    const bool interleaved = (in_sizes[1] == 128 * C_TAB[0]);

    Params p;
    size_t off = 0;
    int bstart = 0;
    for (int t = 0; t < 8; t++) {
        const int C = C_TAB[t];
        const int xi = interleaved ? (3 * t)     : t;
        const int wi = interleaved ? (3 * t + 1) : (8 + t);
        const int bi = interleaved ? (3 * t + 2) : (16 + t);
        const int N  = in_sizes[xi] / C;

        uint32_t fk0, fk1;
        threefry2x32_host(0u, 42u, 0u, (uint32_t)t, fk0, fk1);

        p.e[t].x      = (const float*)d_in[xi];
        p.e[t].W      = (const float*)d_in[wi];
        p.e[t].bias   = (const float*)d_in[bi];
        p.e[t].out    = (float*)d_out + off;
        p.e[t].N      = N;
        p.e[t].C      = C;
        p.e[t].ksteps = C / 32;
        p.e[t].bstart = bstart;
        p.e[t].k0     = fk0;
        p.e[t].k1     = fk1;

        bstart += (N + 127) / 128;
        off += (size_t)N * 128;
    }

    fused_all<<<bstart, 256>>>(p);
}